// round 2
// baseline (speedup 1.0000x reference)
#include <cuda_runtime.h>
#include <math.h>

#define BB 64
#define LL 196
#define DD 2048
#define II 512
#define MM (BB * LL)   // 12544

// Scratch (allocation-free): fv_shaped [B*L, I] and hs_shaped [B, I]
__device__ float g_fvs[MM * II];
__device__ float g_hs[BB * II];

// hs_shaped = hidden @ W_h + b_h   (64x512x512, trivial)
__global__ void hs_kernel(const float* __restrict__ hidden,
                          const float* __restrict__ Wh,
                          const float* __restrict__ bh) {
    int idx = blockIdx.x * blockDim.x + threadIdx.x;   // 0..BB*II
    int b = idx >> 9;
    int i = idx & 511;
    const float* h = hidden + b * II;
    float acc = bh[i];
#pragma unroll 4
    for (int j = 0; j < II; ++j)
        acc = fmaf(h[j], Wh[j * II + i], acc);
    g_hs[idx] = acc;
}

// Classic 128x128 tile, BK=16, 256 threads, 8x8 per thread.
// ADD_HS: epilogue adds g_hs[row/LL][col] (gemm1). Bias always added.
template <bool ADD_HS>
__global__ __launch_bounds__(256, 2)
void sgemm_kernel(const float* __restrict__ A, const float* __restrict__ Bw,
                  const float* __restrict__ bias, float* __restrict__ C,
                  int M, int N, int K) {
    __shared__ float As[16][128];   // transposed: As[k][m]
    __shared__ float Bs[16][128];

    int tid  = threadIdx.x;
    int row0 = blockIdx.y * 128;
    int col0 = blockIdx.x * 128;
    int tx   = tid & 15;            // 0..15 (n)
    int ty   = tid >> 4;            // 0..15 (m)
    int arow = tid >> 2;            // 0..63
    int acol = (tid & 3) * 4;       // 0..12
    int brow = tid >> 5;            // 0..7
    int bcol = (tid & 31) * 4;      // 0..124

    float acc[8][8];
#pragma unroll
    for (int i = 0; i < 8; ++i)
#pragma unroll
        for (int j = 0; j < 8; ++j) acc[i][j] = 0.f;

    for (int kt = 0; kt < K; kt += 16) {
        const float* Ap = A + (size_t)(row0 + arow) * K + kt + acol;
        float4 a0 = *(const float4*)Ap;
        float4 a1 = *(const float4*)(Ap + (size_t)64 * K);
        As[acol + 0][arow]      = a0.x;
        As[acol + 1][arow]      = a0.y;
        As[acol + 2][arow]      = a0.z;
        As[acol + 3][arow]      = a0.w;
        As[acol + 0][arow + 64] = a1.x;
        As[acol + 1][arow + 64] = a1.y;
        As[acol + 2][arow + 64] = a1.z;
        As[acol + 3][arow + 64] = a1.w;

        const float* Bp = Bw + (size_t)(kt + brow) * N + col0 + bcol;
        *(float4*)&Bs[brow][bcol]     = *(const float4*)Bp;
        *(float4*)&Bs[brow + 8][bcol] = *(const float4*)(Bp + (size_t)8 * N);

        __syncthreads();
#pragma unroll
        for (int k = 0; k < 16; ++k) {
            float ra[8], rb[8];
            *(float4*)&ra[0] = *(float4*)&As[k][ty * 8];
            *(float4*)&ra[4] = *(float4*)&As[k][ty * 8 + 4];
            *(float4*)&rb[0] = *(float4*)&Bs[k][tx * 8];
            *(float4*)&rb[4] = *(float4*)&Bs[k][tx * 8 + 4];
#pragma unroll
            for (int i = 0; i < 8; ++i)
#pragma unroll
                for (int j = 0; j < 8; ++j)
                    acc[i][j] = fmaf(ra[i], rb[j], acc[i][j]);
        }
        __syncthreads();
    }

#pragma unroll
    for (int i = 0; i < 8; ++i) {
        int row = row0 + ty * 8 + i;
        const float* hsrow = ADD_HS ? (g_hs + (size_t)(row / LL) * II) : nullptr;
#pragma unroll
        for (int j = 0; j < 8; ++j) {
            int col = col0 + tx * 8 + j;
            float v = acc[i][j] + bias[col];
            if (ADD_HS) v += hsrow[col];
            C[(size_t)row * N + col] = v;
        }
    }
}

// In-place softmax over L (stride DD) on the e/alpha region of d_out,
// plus z = sum_l alpha * fv. One thread per (b, d); fully coalesced.
__global__ void softmax_z_kernel(const float* __restrict__ fv,
                                 float* __restrict__ out) {
    int idx = blockIdx.x * blockDim.x + threadIdx.x;   // 0..BB*DD
    int b = idx / DD;
    int d = idx % DD;
    float* e       = out + BB * DD + (size_t)b * LL * DD + d;
    const float* f = fv + (size_t)b * LL * DD + d;

    // online max + sum
    float m = -INFINITY, s = 0.f;
    for (int l = 0; l < LL; ++l) {
        float v = e[(size_t)l * DD];
        if (v > m) { s *= __expf(m - v); m = v; }
        s += __expf(v - m);
    }
    float inv = 1.f / s;
    float z = 0.f;
    for (int l = 0; l < LL; ++l) {
        size_t off = (size_t)l * DD;
        float p = __expf(e[off] - m) * inv;
        e[off] = p;                       // alpha, in place
        z = fmaf(p, f[off], z);
    }
    out[idx] = z;                         // z region is the first BB*DD floats
}

extern "C" void kernel_launch(void* const* d_in, const int* in_sizes, int n_in,
                              void* d_out, int out_size) {
    const float* fv     = (const float*)d_in[0];
    const float* hidden = (const float*)d_in[1];
    const float* Wf     = (const float*)d_in[2];
    const float* bf     = (const float*)d_in[3];
    const float* Wh     = (const float*)d_in[4];
    const float* bh     = (const float*)d_in[5];
    const float* Wa     = (const float*)d_in[6];
    const float* ba     = (const float*)d_in[7];
    float* out = (float*)d_out;

    void* fvs_ptr = nullptr;
    cudaGetSymbolAddress(&fvs_ptr, g_fvs);
    float* fvs = (float*)fvs_ptr;

    // 1) hidden @ W_h + b_h
    hs_kernel<<<BB * II / 256, 256>>>(hidden, Wh, bh);

    // 2) fv_shaped = fv @ W_f + b_f + hs[b]   (M=12544, N=512, K=2048)
    dim3 g1(II / 128, MM / 128);
    sgemm_kernel<true><<<g1, 256>>>(fv, Wf, bf, fvs, MM, II, DD);

    // 3) e = fv_shaped @ W_a + b_a -> written into alpha region of d_out
    float* e = out + BB * DD;
    dim3 g2(DD / 128, MM / 128);
    sgemm_kernel<false><<<g2, 256>>>(fvs, Wa, ba, e, MM, DD, II);

    // 4) softmax over L (in place) + z
    softmax_z_kernel<<<BB * DD / 256, 256>>>(fv, out);
}

// round 3
// speedup vs baseline: 1.0586x; 1.0586x over previous
#include <cuda_runtime.h>
#include <math.h>

#define BB 64
#define LL 196
#define DD 2048
#define II 512
#define MM (BB * LL)   // 12544

// Scratch (allocation-free): fv_shaped [B*L, I] and hs_shaped [B, I]
__device__ float g_fvs[MM * II];
__device__ float g_hs[BB * II];

// ---------- packed f32x2 helpers ----------
__device__ __forceinline__ unsigned long long pack_dup(float x) {
    unsigned long long r;
    asm("mov.b64 %0, {%1, %1};" : "=l"(r) : "f"(x));
    return r;
}
__device__ __forceinline__ void unpack2(unsigned long long v, float& lo, float& hi) {
    asm("mov.b64 {%0, %1}, %2;" : "=f"(lo), "=f"(hi) : "l"(v));
}
__device__ __forceinline__ void ffma2(unsigned long long& d,
                                      unsigned long long a,
                                      unsigned long long b) {
    asm("fma.rn.f32x2 %0, %1, %2, %0;" : "+l"(d) : "l"(a), "l"(b));
}

// hs_shaped = hidden @ W_h + b_h   (64x512x512, trivial)
__global__ void hs_kernel(const float* __restrict__ hidden,
                          const float* __restrict__ Wh,
                          const float* __restrict__ bh) {
    int idx = blockIdx.x * blockDim.x + threadIdx.x;
    int b = idx >> 9;
    int i = idx & 511;
    const float* h = hidden + b * II;
    float acc = bh[i];
#pragma unroll 4
    for (int j = 0; j < II; ++j)
        acc = fmaf(h[j], Wh[j * II + i], acc);
    g_hs[idx] = acc;
}

// 128x128 tile, BK=16, 256 threads, 8x8 per thread, packed f32x2 math,
// register-prefetch pipelined global loads.
template <bool ADD_HS>
__global__ __launch_bounds__(256, 2)
void sgemm_kernel(const float* __restrict__ A, const float* __restrict__ Bw,
                  const float* __restrict__ bias, float* __restrict__ C,
                  int M, int N, int K) {
    __shared__ float As[16][128];   // transposed: As[k][m]
    __shared__ float Bs[16][128];

    int tid  = threadIdx.x;
    int row0 = blockIdx.y * 128;
    int col0 = blockIdx.x * 128;
    int tx   = tid & 15;            // 0..15 (n)
    int ty   = tid >> 4;            // 0..15 (m)
    int arow = tid >> 2;            // 0..63
    int acol = (tid & 3) * 4;       // 0..12
    int brow = tid >> 5;            // 0..7
    int bcol = (tid & 31) * 4;      // 0..124

    // acc[i][j] packed pairwise along j: acc2[i][j2] = (acc[i][2j2], acc[i][2j2+1])
    unsigned long long acc2[8][4];
#pragma unroll
    for (int i = 0; i < 8; ++i)
#pragma unroll
        for (int j = 0; j < 4; ++j) acc2[i][j] = 0ull;

    // prefetch tile kt=0 into registers
    const float* Ap = A + (size_t)(row0 + arow) * K + acol;
    const float* Bp = Bw + (size_t)brow * N + col0 + bcol;
    float4 pa0 = *(const float4*)Ap;
    float4 pa1 = *(const float4*)(Ap + (size_t)64 * K);
    float4 pb0 = *(const float4*)Bp;
    float4 pb1 = *(const float4*)(Bp + (size_t)8 * N);

    for (int kt = 0; kt < K; kt += 16) {
        // stage current tile into smem
        As[acol + 0][arow]      = pa0.x;
        As[acol + 1][arow]      = pa0.y;
        As[acol + 2][arow]      = pa0.z;
        As[acol + 3][arow]      = pa0.w;
        As[acol + 0][arow + 64] = pa1.x;
        As[acol + 1][arow + 64] = pa1.y;
        As[acol + 2][arow + 64] = pa1.z;
        As[acol + 3][arow + 64] = pa1.w;
        *(float4*)&Bs[brow][bcol]     = pb0;
        *(float4*)&Bs[brow + 8][bcol] = pb1;
        __syncthreads();

        // prefetch next tile
        if (kt + 16 < K) {
            const float* Apn = A + (size_t)(row0 + arow) * K + kt + 16 + acol;
            const float* Bpn = Bw + (size_t)(kt + 16 + brow) * N + col0 + bcol;
            pa0 = *(const float4*)Apn;
            pa1 = *(const float4*)(Apn + (size_t)64 * K);
            pb0 = *(const float4*)Bpn;
            pb1 = *(const float4*)(Bpn + (size_t)8 * N);
        }

#pragma unroll
        for (int k = 0; k < 16; ++k) {
            float ra[8];
            *(float4*)&ra[0] = *(const float4*)&As[k][ty * 8];
            *(float4*)&ra[4] = *(const float4*)&As[k][ty * 8 + 4];
            unsigned long long rb2[4];
            const unsigned long long* brow2 =
                (const unsigned long long*)&Bs[k][tx * 8];
            rb2[0] = brow2[0];
            rb2[1] = brow2[1];
            rb2[2] = brow2[2];
            rb2[3] = brow2[3];
#pragma unroll
            for (int i = 0; i < 8; ++i) {
                unsigned long long aa = pack_dup(ra[i]);
#pragma unroll
                for (int j = 0; j < 4; ++j)
                    ffma2(acc2[i][j], aa, rb2[j]);
            }
        }
        __syncthreads();
    }

#pragma unroll
    for (int i = 0; i < 8; ++i) {
        int row = row0 + ty * 8 + i;
        const float* hsrow = ADD_HS ? (g_hs + (size_t)(row / LL) * II) : nullptr;
        float* crow = C + (size_t)row * N + col0 + tx * 8;
#pragma unroll
        for (int j = 0; j < 4; ++j) {
            float lo, hi;
            unpack2(acc2[i][j], lo, hi);
            int col = col0 + tx * 8 + 2 * j;
            lo += bias[col];
            hi += bias[col + 1];
            if (ADD_HS) { lo += hsrow[col]; hi += hsrow[col + 1]; }
            float2 v = make_float2(lo, hi);
            *(float2*)(crow + 2 * j) = v;
        }
    }
}

// In-place softmax over L (stride DD) on the e/alpha region of d_out,
// plus z = sum_l alpha * fv. One thread per (b, d); fully coalesced.
__global__ void softmax_z_kernel(const float* __restrict__ fv,
                                 float* __restrict__ out) {
    int idx = blockIdx.x * blockDim.x + threadIdx.x;
    int b = idx / DD;
    int d = idx % DD;
    float* e       = out + BB * DD + (size_t)b * LL * DD + d;
    const float* f = fv + (size_t)b * LL * DD + d;

    float m = -INFINITY, s = 0.f;
    for (int l = 0; l < LL; ++l) {
        float v = e[(size_t)l * DD];
        if (v > m) { s *= __expf(m - v); m = v; }
        s += __expf(v - m);
    }
    float inv = 1.f / s;
    float z = 0.f;
    for (int l = 0; l < LL; ++l) {
        size_t off = (size_t)l * DD;
        float p = __expf(e[off] - m) * inv;
        e[off] = p;
        z = fmaf(p, f[off], z);
    }
    out[idx] = z;
}

extern "C" void kernel_launch(void* const* d_in, const int* in_sizes, int n_in,
                              void* d_out, int out_size) {
    const float* fv     = (const float*)d_in[0];
    const float* hidden = (const float*)d_in[1];
    const float* Wf     = (const float*)d_in[2];
    const float* bf     = (const float*)d_in[3];
    const float* Wh     = (const float*)d_in[4];
    const float* bh     = (const float*)d_in[5];
    const float* Wa     = (const float*)d_in[6];
    const float* ba     = (const float*)d_in[7];
    float* out = (float*)d_out;

    void* fvs_ptr = nullptr;
    cudaGetSymbolAddress(&fvs_ptr, g_fvs);
    float* fvs = (float*)fvs_ptr;

    hs_kernel<<<BB * II / 256, 256>>>(hidden, Wh, bh);

    dim3 g1(II / 128, MM / 128);
    sgemm_kernel<true><<<g1, 256>>>(fv, Wf, bf, fvs, MM, II, DD);

    float* e = out + BB * DD;
    dim3 g2(DD / 128, MM / 128);
    sgemm_kernel<false><<<g2, 256>>>(fvs, Wa, ba, e, MM, DD, II);

    softmax_z_kernel<<<BB * DD / 256, 256>>>(fv, out);
}

// round 5
// speedup vs baseline: 2.3580x; 2.2274x over previous
#include <cuda_runtime.h>
#include <cuda_bf16.h>
#include <stdint.h>
#include <math.h>

#define BB 64
#define LL 196
#define DD 2048
#define II 512
#define MM (BB * LL)   // 12544

typedef __nv_bfloat16 bf16;

// ---------------- device scratch (allocation-free) ----------------
__device__ bf16 g_fv_hi[(size_t)MM * DD];
__device__ bf16 g_fv_lo[(size_t)MM * DD];
__device__ bf16 g_fvs_hi[(size_t)MM * II];
__device__ bf16 g_fvs_lo[(size_t)MM * II];
__device__ bf16 g_WfT_hi[(size_t)II * DD];   // [I, D] K-major
__device__ bf16 g_WfT_lo[(size_t)II * DD];
__device__ bf16 g_WaT_hi[(size_t)DD * II];   // [D, I] K-major
__device__ bf16 g_WaT_lo[(size_t)DD * II];
__device__ float g_hs[BB * II];

// ---------------- helpers ----------------
__device__ __forceinline__ uint32_t smem_u32(const void* p) {
    uint32_t a;
    asm("{ .reg .u64 t; cvta.to.shared.u64 t, %1; cvt.u32.u64 %0, t; }"
        : "=r"(a) : "l"(p));
    return a;
}
__device__ __forceinline__ void cp_async16(uint32_t s, const void* g) {
    asm volatile("cp.async.cg.shared.global [%0], [%1], 16;" :: "r"(s), "l"(g));
}
__device__ __forceinline__ void cp_commit() {
    asm volatile("cp.async.commit_group;" ::: "memory");
}
__device__ __forceinline__ void cp_wait1() {
    asm volatile("cp.async.wait_group 1;" ::: "memory");
}
__device__ __forceinline__ void cp_wait0() {
    asm volatile("cp.async.wait_group 0;" ::: "memory");
}
__device__ __forceinline__ void ldsm4(uint32_t& r0, uint32_t& r1, uint32_t& r2,
                                      uint32_t& r3, uint32_t addr) {
    asm volatile("ldmatrix.sync.aligned.m8n8.x4.shared.b16 {%0,%1,%2,%3}, [%4];"
                 : "=r"(r0), "=r"(r1), "=r"(r2), "=r"(r3) : "r"(addr));
}
__device__ __forceinline__ void mma16816(float* c, const uint32_t* a,
                                         const uint32_t* b) {
    asm volatile(
        "mma.sync.aligned.m16n8k16.row.col.f32.bf16.bf16.f32 "
        "{%0,%1,%2,%3}, {%4,%5,%6,%7}, {%8,%9}, {%0,%1,%2,%3};"
        : "+f"(c[0]), "+f"(c[1]), "+f"(c[2]), "+f"(c[3])
        : "r"(a[0]), "r"(a[1]), "r"(a[2]), "r"(a[3]), "r"(b[0]), "r"(b[1]));
}

__device__ __forceinline__ void split1(float v, bf16& h, bf16& l) {
    h = __float2bfloat16_rn(v);
    l = __float2bfloat16_rn(v - __bfloat162float(h));
}

// ---------------- conversion kernels ----------------
__global__ void split_fv_kernel(const float* __restrict__ in) {
    size_t i = (size_t)blockIdx.x * blockDim.x + threadIdx.x;   // MM*DD/2
    float2 v = ((const float2*)in)[i];
    bf16 h0, l0, h1, l1;
    split1(v.x, h0, l0);
    split1(v.y, h1, l1);
    ((__nv_bfloat162*)g_fv_hi)[i] = __nv_bfloat162(h0, h1);
    ((__nv_bfloat162*)g_fv_lo)[i] = __nv_bfloat162(l0, l1);
}

// transpose [K,N] fp32 -> [N,K] bf16 hi/lo
__global__ void transpose_split_kernel(const float* __restrict__ in,
                                       bf16* __restrict__ ohi,
                                       bf16* __restrict__ olo,
                                       int K, int N) {
    __shared__ float t[32][33];
    int n0 = blockIdx.x * 32, k0 = blockIdx.y * 32;
    int tx = threadIdx.x, ty = threadIdx.y;   // (32, 8)
#pragma unroll
    for (int i = 0; i < 32; i += 8)
        t[ty + i][tx] = in[(size_t)(k0 + ty + i) * N + n0 + tx];
    __syncthreads();
#pragma unroll
    for (int i = 0; i < 32; i += 8) {
        float v = t[tx][ty + i];
        bf16 h, l;
        split1(v, h, l);
        size_t o = (size_t)(n0 + ty + i) * K + k0 + tx;
        ohi[o] = h;
        olo[o] = l;
    }
}

// hs = hidden @ W_h + b_h  (fp32, tiny)
__global__ void hs_kernel(const float* __restrict__ hidden,
                          const float* __restrict__ Wh,
                          const float* __restrict__ bh) {
    int idx = blockIdx.x * blockDim.x + threadIdx.x;
    int b = idx >> 9;
    int i = idx & 511;
    const float* h = hidden + b * II;
    float acc = bh[i];
#pragma unroll 4
    for (int j = 0; j < II; ++j)
        acc = fmaf(h[j], Wh[j * II + i], acc);
    g_hs[idx] = acc;
}

// ---------------- tensor-core (mma.sync) GEMM ----------------
// A [M,K0] row-major, B stored [N,K0] K-major; C = A@B^T.
// 3-way bf16 split folded in: passes (hi,hi), (lo,hi), (hi,lo).
// Tile: 128x128, BK=64, 8 warps (each 64x32), double-buffered cp.async.
// Smem tile layout: [row][64 bf16] per 128B row, swizzled:
//   byteoff = row*128 + (cb ^ ((row&7)<<4))

__device__ __forceinline__ void load_tile_async(uint32_t dst, const bf16* src,
                                                int ldk, int tid) {
    // 128 rows x 128 bytes = 1024 x 16B chunks; 256 threads x 4 chunks
#pragma unroll
    for (int i = 0; i < 4; ++i) {
        int chunk = i * 256 + tid;
        int r = chunk >> 3, c16 = chunk & 7;
        const char* g = (const char*)src + (size_t)r * ldk * 2 + c16 * 16;
        uint32_t cb = c16 * 16;
        uint32_t s = dst + r * 128 + (cb ^ ((r & 7) << 4));
        cp_async16(s, g);
    }
}

template <int EPI>
__global__ __launch_bounds__(256, 2)
void mma_gemm(const bf16* __restrict__ Ahi, const bf16* __restrict__ Alo,
              const bf16* __restrict__ Bhi, const bf16* __restrict__ Blo,
              const float* __restrict__ bias,
              float* __restrict__ Cf, bf16* __restrict__ Chi,
              bf16* __restrict__ Clo, int N, int K0) {
    extern __shared__ char smem[];
    uint32_t sbase = smem_u32(smem);
    int tid = threadIdx.x, lane = tid & 31, wid = tid >> 5;
    int warp_m = wid >> 2, warp_n = wid & 3;
    int row0 = blockIdx.y * 128, col0 = blockIdx.x * 128;

    float c[4][4][4];
#pragma unroll
    for (int mi = 0; mi < 4; ++mi)
#pragma unroll
        for (int ni = 0; ni < 4; ++ni)
#pragma unroll
            for (int f = 0; f < 4; ++f) c[mi][ni][f] = 0.f;

    int kc = K0 / 64;
    int nch = 3 * kc;

    // --- issue loads for chunk cc into buffer cc&1 ---
    auto issue = [&](int cc) {
        int buf = cc & 1;
        int phase = cc / kc;
        int kk = (cc - phase * kc) * 64;
        const bf16* As = (phase == 1) ? Alo : Ahi;
        const bf16* Bs = (phase == 2) ? Blo : Bhi;
        load_tile_async(sbase + buf * 32768, As + (size_t)row0 * K0 + kk, K0, tid);
        load_tile_async(sbase + buf * 32768 + 16384, Bs + (size_t)col0 * K0 + kk, K0, tid);
        cp_commit();
    };

    issue(0);

    int la15 = lane & 15, la7 = lane & 7;
    int a_cbsel = (lane >> 4) * 16;
    int b_cbsel = ((lane >> 3) & 1) * 16;
    int b_rowsel = (lane >> 4) * 8;

    for (int cc = 0; cc < nch; ++cc) {
        if (cc + 1 < nch) { issue(cc + 1); cp_wait1(); }
        else              { cp_wait0(); }
        __syncthreads();

        uint32_t sA = sbase + (cc & 1) * 32768;
        uint32_t sB = sA + 16384;
#pragma unroll
        for (int ks = 0; ks < 4; ++ks) {
            uint32_t a[4][4];
#pragma unroll
            for (int mi = 0; mi < 4; ++mi) {
                int row = warp_m * 64 + mi * 16 + la15;
                uint32_t cb = ks * 32 + a_cbsel;
                uint32_t addr = sA + row * 128 + (cb ^ ((row & 7) << 4));
                ldsm4(a[mi][0], a[mi][1], a[mi][2], a[mi][3], addr);
            }
            uint32_t b[4][2];
#pragma unroll
            for (int nb = 0; nb < 2; ++nb) {
                int row = warp_n * 32 + nb * 16 + la7 + b_rowsel;
                uint32_t cb = ks * 32 + b_cbsel;
                uint32_t addr = sB + row * 128 + (cb ^ ((row & 7) << 4));
                ldsm4(b[2 * nb][0], b[2 * nb][1], b[2 * nb + 1][0], b[2 * nb + 1][1], addr);
            }
#pragma unroll
            for (int mi = 0; mi < 4; ++mi)
#pragma unroll
                for (int ni = 0; ni < 4; ++ni)
                    mma16816(c[mi][ni], a[mi], b[ni]);
        }
        __syncthreads();
    }

    // ---------------- epilogue ----------------
    int g = lane >> 2, tg = lane & 3;
#pragma unroll
    for (int mi = 0; mi < 4; ++mi) {
#pragma unroll
        for (int half = 0; half < 2; ++half) {
            int row = row0 + warp_m * 64 + mi * 16 + g + half * 8;
            const float* hsrow = (EPI == 0) ? (g_hs + (size_t)(row / LL) * II) : nullptr;
#pragma unroll
            for (int ni = 0; ni < 4; ++ni) {
                int col = col0 + warp_n * 32 + ni * 8 + tg * 2;
                float v0 = c[mi][ni][2 * half + 0];
                float v1 = c[mi][ni][2 * half + 1];
                v0 += bias[col];
                v1 += bias[col + 1];
                if (EPI == 0) {
                    v0 += hsrow[col];
                    v1 += hsrow[col + 1];
                    bf16 h0, l0, h1, l1;
                    split1(v0, h0, l0);
                    split1(v1, h1, l1);
                    size_t o = (size_t)row * N + col;
                    *(__nv_bfloat162*)(Chi + o) = __nv_bfloat162(h0, h1);
                    *(__nv_bfloat162*)(Clo + o) = __nv_bfloat162(l0, l1);
                } else {
                    *(float2*)(Cf + (size_t)row * N + col) = make_float2(v0, v1);
                }
            }
        }
    }
}

// ---------------- softmax + z ----------------
__global__ void softmax_z_kernel(const float* __restrict__ fv,
                                 float* __restrict__ out) {
    int idx = blockIdx.x * blockDim.x + threadIdx.x;
    int b = idx / DD;
    int d = idx % DD;
    float* e       = out + BB * DD + (size_t)b * LL * DD + d;
    const float* f = fv + (size_t)b * LL * DD + d;

    float m = -INFINITY, s = 0.f;
    for (int l = 0; l < LL; ++l) {
        float v = e[(size_t)l * DD];
        if (v > m) { s *= __expf(m - v); m = v; }
        s += __expf(v - m);
    }
    float inv = 1.f / s;
    float z = 0.f;
    for (int l = 0; l < LL; ++l) {
        size_t off = (size_t)l * DD;
        float p = __expf(e[off] - m) * inv;
        e[off] = p;
        z = fmaf(p, f[off], z);
    }
    out[idx] = z;
}

// ---------------- launch ----------------
#define GEMM_SMEM 65536

extern "C" void kernel_launch(void* const* d_in, const int* in_sizes, int n_in,
                              void* d_out, int out_size) {
    const float* fv     = (const float*)d_in[0];
    const float* hidden = (const float*)d_in[1];
    const float* Wf     = (const float*)d_in[2];
    const float* bf     = (const float*)d_in[3];
    const float* Wh     = (const float*)d_in[4];
    const float* bh     = (const float*)d_in[5];
    const float* Wa     = (const float*)d_in[6];
    const float* ba     = (const float*)d_in[7];
    float* out = (float*)d_out;

    cudaFuncSetAttribute(mma_gemm<0>, cudaFuncAttributeMaxDynamicSharedMemorySize, GEMM_SMEM);
    cudaFuncSetAttribute(mma_gemm<1>, cudaFuncAttributeMaxDynamicSharedMemorySize, GEMM_SMEM);

    void* p;
    cudaGetSymbolAddress(&p, g_fv_hi);   bf16* fv_hi  = (bf16*)p;
    cudaGetSymbolAddress(&p, g_fv_lo);   bf16* fv_lo  = (bf16*)p;
    cudaGetSymbolAddress(&p, g_fvs_hi);  bf16* fvs_hi = (bf16*)p;
    cudaGetSymbolAddress(&p, g_fvs_lo);  bf16* fvs_lo = (bf16*)p;
    cudaGetSymbolAddress(&p, g_WfT_hi);  bf16* WfT_hi = (bf16*)p;
    cudaGetSymbolAddress(&p, g_WfT_lo);  bf16* WfT_lo = (bf16*)p;
    cudaGetSymbolAddress(&p, g_WaT_hi);  bf16* WaT_hi = (bf16*)p;
    cudaGetSymbolAddress(&p, g_WaT_lo);  bf16* WaT_lo = (bf16*)p;

    // input conversions (independent)
    split_fv_kernel<<<(size_t)MM * DD / 2 / 256, 256>>>(fv);
    hs_kernel<<<BB * II / 256, 256>>>(hidden, Wh, bh);
    transpose_split_kernel<<<dim3(II / 32, DD / 32), dim3(32, 8)>>>(Wf, WfT_hi, WfT_lo, DD, II);
    transpose_split_kernel<<<dim3(DD / 32, II / 32), dim3(32, 8)>>>(Wa, WaT_hi, WaT_lo, II, DD);

    // gemm1: fvs = fv @ Wf + bf + hs   (M=12544, N=512, K0=2048) -> bf16 hi/lo
    mma_gemm<0><<<dim3(II / 128, MM / 128), 256, GEMM_SMEM>>>(
        fv_hi, fv_lo, WfT_hi, WfT_lo, bf, nullptr, fvs_hi, fvs_lo, II, DD);

    // gemm2: e = fvs @ Wa + ba   (M=12544, N=2048, K0=512) -> fp32 into out
    float* e = out + BB * DD;
    mma_gemm<1><<<dim3(DD / 128, MM / 128), 256, GEMM_SMEM>>>(
        fvs_hi, fvs_lo, WaT_hi, WaT_lo, ba, e, nullptr, nullptr, DD, II);

    // softmax over L (in place) + z
    softmax_z_kernel<<<BB * DD / 256, 256>>>(fv, out);
}